// round 12
// baseline (speedup 1.0000x reference)
#include <cuda_runtime.h>
#include <cstdint>

#define XS_STRIDE 132   // words: 128 + 4 pad — conflict-free ldmatrix
#define WS_STRIDE 136   // words: 128 + 8 pad — conflict-free scalar B loads

// smem byte offsets
#define OFF_A   0         // X tile / ctx: 128 x 132 words (67584 B)
#define OFF_B0  67584     // W buffer 0:   128 x 136 words (69632 B)
#define OFF_B1  137216    // W buffer 1:   128 x 136 words (69632 B)
#define OFF_MS  206848    // 128 mask words (512 B)
#define SMEM_BYTES 207360

// pre-rounded (tf32) weights: Wq, Wk, Wv, Wo
__device__ float W_rnd[4][16384];

static __device__ __forceinline__ uint32_t f2tf(float f) {
    uint32_t r; asm("cvt.rna.tf32.f32 %0, %1;" : "=r"(r) : "f"(f)); return r;
}

static __device__ __forceinline__ void mma_tf32(float* d,
        uint32_t a0, uint32_t a1, uint32_t a2, uint32_t a3,
        uint32_t b0, uint32_t b1) {
    asm volatile(
        "mma.sync.aligned.m16n8k8.row.col.f32.tf32.tf32.f32 "
        "{%0,%1,%2,%3}, {%4,%5,%6,%7}, {%8,%9}, {%0,%1,%2,%3};\n"
        : "+f"(d[0]), "+f"(d[1]), "+f"(d[2]), "+f"(d[3])
        : "r"(a0), "r"(a1), "r"(a2), "r"(a3), "r"(b0), "r"(b1));
}

static __device__ __forceinline__ void ldsm_x4(uint32_t& r0, uint32_t& r1,
        uint32_t& r2, uint32_t& r3, uint32_t saddr) {
    asm volatile("ldmatrix.sync.aligned.m8n8.x4.shared.b16 {%0,%1,%2,%3}, [%4];"
                 : "=r"(r0), "=r"(r1), "=r"(r2), "=r"(r3) : "r"(saddr));
}

#define CP_COMMIT()  asm volatile("cp.async.commit_group;" ::: "memory")
#define CP_WAIT(n)   asm volatile("cp.async.wait_group %0;" :: "n"(n) : "memory")

// ---- prep: round all four W matrices to tf32 (rna) into W_rnd ----
__global__ void prep_kernel(const float* __restrict__ Wq, const float* __restrict__ Wk,
                            const float* __restrict__ Wv, const float* __restrict__ Wo)
{
    const int i = blockIdx.x * blockDim.x + threadIdx.x;   // 0..4095 float4 slots
    const float* src[4] = {Wq, Wk, Wv, Wo};
    #pragma unroll
    for (int g = 0; g < 4; g++) {
        float4 v = *(const float4*)(src[g] + i * 4);
        float4 o;
        o.x = __uint_as_float(f2tf(v.x));
        o.y = __uint_as_float(f2tf(v.y));
        o.z = __uint_as_float(f2tf(v.z));
        o.w = __uint_as_float(f2tf(v.w));
        *(float4*)(&W_rnd[g][i * 4]) = o;
    }
}

__global__ __launch_bounds__(256, 1)
void laa_kernel(const float* __restrict__ x, const uint32_t* __restrict__ mask,
                const float* __restrict__ bq, const float* __restrict__ bk,
                const float* __restrict__ bv, const float* __restrict__ bo,
                float* __restrict__ out)
{
    extern __shared__ char smem[];
    uint32_t* Xs    = (uint32_t*)(smem + OFF_A);
    uint32_t* Bs0   = (uint32_t*)(smem + OFF_B0);
    uint32_t* Bs1   = (uint32_t*)(smem + OFF_B1);
    uint32_t* maskS = (uint32_t*)(smem + OFF_MS);

    const int tid  = threadIdx.x;
    const int lane = tid & 31;
    const int w    = tid >> 5;     // 0..7
    const int gid  = lane >> 2;    // 0..7
    const int tig  = lane & 3;     // 0..3
    const int wm   = w >> 1;       // 0..3: rows 32*wm..
    const int wn   = w & 1;        // 64-col slab (2 heads)
    const int row0 = blockIdx.x * 128;

    // async W copy from pre-rounded scratch
    auto cpW = [&](const float* __restrict__ W, uint32_t* Ws) {
        #pragma unroll
        for (int i = 0; i < 16; i++) {
            int fi = tid + i * 256;          // 0..4095 float4 slots
            int r = fi >> 5, c4 = fi & 31;
            uint32_t d = (uint32_t)__cvta_generic_to_shared(Ws + r * WS_STRIDE + c4 * 4);
            asm volatile("cp.async.cg.shared.global [%0], [%1], 16;"
                         :: "r"(d), "l"(W + r * 128 + c4 * 4) : "memory");
        }
    };

    // ---- kick off Wq, Wk copies (group 0), overlap with X staging ----
    cpW(W_rnd[0], Bs0);
    cpW(W_rnd[1], Bs1);
    CP_COMMIT();

    // ---- stage X tile (128x128 f32 -> tf32, cvt.rna) ----
    #pragma unroll
    for (int i = 0; i < 16; i++) {
        int fi = tid + i * 256;              // 0..4095 float4 slots
        int r = fi >> 5, c4 = fi & 31;
        float4 v = *(const float4*)(x + (size_t)(row0 + r) * 128 + c4 * 4);
        uint4 u; u.x = f2tf(v.x); u.y = f2tf(v.y); u.z = f2tf(v.z); u.w = f2tf(v.w);
        *(uint4*)(Xs + r * XS_STRIDE + c4 * 4) = u;
    }
    if (tid < 128) maskS[tid] = mask[row0 + tid];
    CP_WAIT(0);
    __syncthreads();

    // ldmatrix bases for the two 16-row m-fragments of this warp's 32-row slab
    const int a_row = wm * 32 + (lane & 15);
    const uint32_t a_base0 =
        (uint32_t)__cvta_generic_to_shared(Xs + a_row * XS_STRIDE + ((lane >> 4) & 1) * 4);
    const uint32_t a_base1 = a_base0 + 16 * XS_STRIDE * 4;

    const int colb = wn * 64 + 2 * tig;       // acc cols (colb, colb+1) + n*8

    // GEMM: acc = Xs(128x128) @ Ws(128x128); warp tile 32x64 (8 n-frags)
    auto gemm = [&](float acc[2][8][4], const uint32_t* Ws) {
        #pragma unroll
        for (int mf = 0; mf < 2; mf++)
            #pragma unroll
            for (int n = 0; n < 8; n++)
                #pragma unroll
                for (int j = 0; j < 4; j++) acc[mf][n][j] = 0.f;
        #pragma unroll
        for (int kk = 0; kk < 16; kk++) {
            const int k0 = kk * 8;
            uint32_t a0[2], a1[2], a2[2], a3[2];
            ldsm_x4(a0[0], a1[0], a2[0], a3[0], a_base0 + (uint32_t)(k0 * 4));
            ldsm_x4(a0[1], a1[1], a2[1], a3[1], a_base1 + (uint32_t)(k0 * 4));
            const uint32_t* bp = Ws + (k0 + tig) * WS_STRIDE + wn * 64 + gid;
            uint32_t b[8][2];
            #pragma unroll
            for (int n = 0; n < 8; n++) {
                b[n][0] = bp[n * 8];
                b[n][1] = bp[4 * WS_STRIDE + n * 8];
            }
            #pragma unroll
            for (int mf = 0; mf < 2; mf++)
                #pragma unroll
                for (int n = 0; n < 8; n++)
                    mma_tf32(acc[mf][n], a0[mf], a1[mf], a2[mf], a3[mf],
                             b[n][0], b[n][1]);
        }
    };

    auto bias_add = [&](float acc[2][8][4], const float* __restrict__ bias) {
        #pragma unroll
        for (int n = 0; n < 8; n++) {
            float2 bb = __ldg((const float2*)(bias + colb + n * 8));
            #pragma unroll
            for (int mf = 0; mf < 2; mf++) {
                acc[mf][n][0] += bb.x; acc[mf][n][1] += bb.y;
                acc[mf][n][2] += bb.x; acc[mf][n][3] += bb.y;
            }
        }
    };

    float P[2][2][2][4];  // attention weights per (mf, half, head-in-slab, key atom)
    float rv[2][2];       // residue-valid flag per (mf, half)
    {
        // ---- Q GEMM ----
        float Qa[2][8][4];
        gemm(Qa, Bs0);
        bias_add(Qa, bq);
        __syncthreads();                 // all warps done reading Bs0

        // Wv -> Bs0 flows during K GEMM + softmax (group 1)
        cpW(W_rnd[2], Bs0);
        CP_COMMIT();

        // ---- K GEMM ----
        float Ka[2][8][4];
        gemm(Ka, Bs1);
        bias_add(Ka, bk);

        // ---- scores + softmax (2 heads per warp), registers + shuffles ----
        #pragma unroll
        for (int mf = 0; mf < 2; mf++) {
            #pragma unroll
            for (int half = 0; half < 2; half++) {
                const int rowg = wm * 32 + mf * 16 + half * 8 + gid;
                const int rb   = rowg & ~3;
                float vb[4];
                #pragma unroll
                for (int e = 0; e < 4; e++)
                    vb[e] = (maskS[rb | e] != 0u) ? 1.f : 0.f;
                float any = vb[0] + vb[1] + vb[2] + vb[3];
                rv[mf][half] = (any > 0.f) ? 1.f : 0.f;
                #pragma unroll
                for (int hh = 0; hh < 2; hh++) {
                    float sc[4];
                    #pragma unroll
                    for (int e = 0; e < 4; e++) {
                        const int src = (lane & ~12) | (e << 2);
                        float s = 0.f;
                        #pragma unroll
                        for (int nn = 0; nn < 4; nn++) {
                            const int n = hh * 4 + nn;
                            #pragma unroll
                            for (int dj = 0; dj < 2; dj++) {
                                int j = half * 2 + dj;
                                s = fmaf(Qa[mf][n][j],
                                         __shfl_sync(0xffffffffu, Ka[mf][n][j], src), s);
                            }
                        }
                        s += __shfl_xor_sync(0xffffffffu, s, 1);
                        s += __shfl_xor_sync(0xffffffffu, s, 2);
                        sc[e] = (vb[e] > 0.f) ? s * 0.17677669529663687f : -1e30f;
                    }
                    float mx = fmaxf(fmaxf(sc[0], sc[1]), fmaxf(sc[2], sc[3]));
                    float ps = 0.f, pe[4];
                    #pragma unroll
                    for (int e = 0; e < 4; e++) {
                        pe[e] = (vb[e] > 0.f) ? __expf(sc[e] - mx) : 0.f;
                        ps += pe[e];
                    }
                    float inv = (any > 0.f) ? (1.f / ps) : 0.f;
                    #pragma unroll
                    for (int e = 0; e < 4; e++) P[mf][half][hh][e] = pe[e] * inv;
                }
            }
        }
    }   // Qa, Ka dead

    __syncthreads();                 // all warps done reading Bs1 (K GEMM)

    // Wo -> Bs1 flows during V GEMM + P.V + ctx write (group 2)
    cpW(W_rnd[3], Bs1);
    CP_COMMIT();
    CP_WAIT(1);                      // Wv (group 1) arrived
    __syncthreads();                 // Wv visible to all warps

    // ---- V GEMM + P·V (registers) ----
    float cx[2][8][4];
    {
        float Va[2][8][4];
        gemm(Va, Bs0);
        bias_add(Va, bv);
        #pragma unroll
        for (int mf = 0; mf < 2; mf++)
            #pragma unroll
            for (int n = 0; n < 8; n++)
                #pragma unroll
                for (int j = 0; j < 4; j++) cx[mf][n][j] = 0.f;
        #pragma unroll
        for (int mf = 0; mf < 2; mf++) {
            #pragma unroll
            for (int half = 0; half < 2; half++) {
                #pragma unroll
                for (int hh = 0; hh < 2; hh++) {
                    #pragma unroll
                    for (int e = 0; e < 4; e++) {
                        const int src = (lane & ~12) | (e << 2);
                        const float pw = P[mf][half][hh][e];
                        #pragma unroll
                        for (int nn = 0; nn < 4; nn++) {
                            const int n = hh * 4 + nn;
                            #pragma unroll
                            for (int dj = 0; dj < 2; dj++) {
                                int j = half * 2 + dj;
                                cx[mf][n][j] = fmaf(pw,
                                    __shfl_sync(0xffffffffu, Va[mf][n][j], src),
                                    cx[mf][n][j]);
                            }
                        }
                    }
                }
            }
        }
    }   // Va dead

    __syncthreads();            // all warps done reading Xs (V GEMM)

    // ---- ctx -> Xs (tf32, cvt.rna) ----
    #pragma unroll
    for (int mf = 0; mf < 2; mf++) {
        #pragma unroll
        for (int half = 0; half < 2; half++) {
            const int rowg = wm * 32 + mf * 16 + half * 8 + gid;
            #pragma unroll
            for (int n = 0; n < 8; n++) {
                uint2 u;
                u.x = f2tf(cx[mf][n][half * 2 + 0]);
                u.y = f2tf(cx[mf][n][half * 2 + 1]);
                *(uint2*)(Xs + rowg * XS_STRIDE + colb + n * 8) = u;
            }
        }
    }
    CP_WAIT(0);                 // Wo (group 2) arrived
    __syncthreads();            // ctx + Wo visible

    // ---- O GEMM + bias + residue zeroing -> global ----
    {
        float Oa[2][8][4];
        gemm(Oa, Bs1);
        bias_add(Oa, bo);
        #pragma unroll
        for (int mf = 0; mf < 2; mf++) {
            #pragma unroll
            for (int half = 0; half < 2; half++) {
                const int rowg = wm * 32 + mf * 16 + half * 8 + gid;
                const float r = rv[mf][half];
                #pragma unroll
                for (int n = 0; n < 8; n++) {
                    float2 o;
                    o.x = Oa[mf][n][half * 2 + 0] * r;
                    o.y = Oa[mf][n][half * 2 + 1] * r;
                    *(float2*)(out + (size_t)(row0 + rowg) * 128 + colb + n * 8) = o;
                }
            }
        }
    }
}

extern "C" void kernel_launch(void* const* d_in, const int* in_sizes, int n_in,
                              void* d_out, int out_size)
{
    const float*    x    = (const float*)d_in[0];
    const uint32_t* mask = (const uint32_t*)d_in[1];
    const float*    Wq   = (const float*)d_in[2];
    const float*    bq   = (const float*)d_in[3];
    const float*    Wk   = (const float*)d_in[4];
    const float*    bk   = (const float*)d_in[5];
    const float*    Wv   = (const float*)d_in[6];
    const float*    bv   = (const float*)d_in[7];
    const float*    Wo   = (const float*)d_in[8];
    const float*    bo   = (const float*)d_in[9];
    float* out = (float*)d_out;

    const int rows = in_sizes[0] / 128;   // 131072
    const int grid = rows / 128;          // 1024

    prep_kernel<<<16, 256>>>(Wq, Wk, Wv, Wo);

    cudaFuncSetAttribute(laa_kernel, cudaFuncAttributeMaxDynamicSharedMemorySize, SMEM_BYTES);
    laa_kernel<<<grid, 256, SMEM_BYTES>>>(x, mask, bq, bk, bv, bo, out);
}

// round 13
// speedup vs baseline: 1.0446x; 1.0446x over previous
#include <cuda_runtime.h>
#include <cstdint>

#define XS_STRIDE 132   // words: 128 + 4 pad — conflict-free ldmatrix (A)
#define WT_STRIDE 132   // words: 128 + 4 pad — conflict-free ldmatrix (B, n-major)

// smem byte offsets
#define OFF_A   0         // X tile / ctx: 128 x 132 words (67584 B)
#define OFF_B0  67584     // W^T buffer 0: 128 x 132 words (67584 B)
#define OFF_B1  135168    // W^T buffer 1: 128 x 132 words (67584 B)
#define OFF_MS  202752    // 128 mask words (512 B)
#define SMEM_BYTES 203264

// pre-rounded (tf32, rna) TRANSPOSED weights: WT[g][n][k], g = q,k,v,o
__device__ float WT_rnd[4][16384];

static __device__ __forceinline__ uint32_t f2tf(float f) {
    uint32_t r; asm("cvt.rna.tf32.f32 %0, %1;" : "=r"(r) : "f"(f)); return r;
}

static __device__ __forceinline__ void mma_tf32(float* d,
        uint32_t a0, uint32_t a1, uint32_t a2, uint32_t a3,
        uint32_t b0, uint32_t b1) {
    asm volatile(
        "mma.sync.aligned.m16n8k8.row.col.f32.tf32.tf32.f32 "
        "{%0,%1,%2,%3}, {%4,%5,%6,%7}, {%8,%9}, {%0,%1,%2,%3};\n"
        : "+f"(d[0]), "+f"(d[1]), "+f"(d[2]), "+f"(d[3])
        : "r"(a0), "r"(a1), "r"(a2), "r"(a3), "r"(b0), "r"(b1));
}

static __device__ __forceinline__ void ldsm_x4(uint32_t& r0, uint32_t& r1,
        uint32_t& r2, uint32_t& r3, uint32_t saddr) {
    asm volatile("ldmatrix.sync.aligned.m8n8.x4.shared.b16 {%0,%1,%2,%3}, [%4];"
                 : "=r"(r0), "=r"(r1), "=r"(r2), "=r"(r3) : "r"(saddr));
}

#define CP_COMMIT()  asm volatile("cp.async.commit_group;" ::: "memory")
#define CP_WAIT(n)   asm volatile("cp.async.wait_group %0;" :: "n"(n) : "memory")

// ---- prep: round to tf32 (rna) AND transpose: WT[g][n][k] = rna(W[g][k][n]) ----
__global__ void prep_kernel(const float* __restrict__ Wq, const float* __restrict__ Wk,
                            const float* __restrict__ Wv, const float* __restrict__ Wo)
{
    const int t = blockIdx.x * blockDim.x + threadIdx.x;   // 0..4095
    const float* src[4] = {Wq, Wk, Wv, Wo};
    #pragma unroll
    for (int i = 0; i < 4; i++) {
        int idx = t + i * 4096;            // 0..16383
        int g   = idx >> 12;
        int r   = idx & 4095;
        int k4  = r >> 7;                  // k-chunk 0..31 (4 k per chunk)
        int n   = r & 127;                 // consecutive lanes -> consecutive n (coalesced reads)
        const float* W = src[g];
        float4 o;
        o.x = __uint_as_float(f2tf(W[(4 * k4 + 0) * 128 + n]));
        o.y = __uint_as_float(f2tf(W[(4 * k4 + 1) * 128 + n]));
        o.z = __uint_as_float(f2tf(W[(4 * k4 + 2) * 128 + n]));
        o.w = __uint_as_float(f2tf(W[(4 * k4 + 3) * 128 + n]));
        *(float4*)(&WT_rnd[g][n * 128 + 4 * k4]) = o;
    }
}

__global__ __launch_bounds__(512, 1)
void laa_kernel(const float* __restrict__ x, const uint32_t* __restrict__ mask,
                const float* __restrict__ bq, const float* __restrict__ bk,
                const float* __restrict__ bv, const float* __restrict__ bo,
                float* __restrict__ out)
{
    extern __shared__ char smem[];
    uint32_t* Xs    = (uint32_t*)(smem + OFF_A);
    uint32_t* Bs0   = (uint32_t*)(smem + OFF_B0);
    uint32_t* Bs1   = (uint32_t*)(smem + OFF_B1);
    uint32_t* maskS = (uint32_t*)(smem + OFF_MS);

    const int tid  = threadIdx.x;
    const int lane = tid & 31;
    const int w    = tid >> 5;     // 0..15
    const int gid  = lane >> 2;    // 0..7
    const int tig  = lane & 3;     // 0..3
    const int wm   = w >> 2;       // row group: rows 32*wm..
    const int wn   = w & 3;        // col slab = head wn
    const int row0 = blockIdx.x * 128;

    // async W^T copy from pre-rounded scratch: 128 n-rows x 128 k-words
    auto cpW = [&](const float* __restrict__ WT, uint32_t* Ws) {
        #pragma unroll
        for (int i = 0; i < 8; i++) {
            int fi = tid + i * 512;          // 0..4095 float4 slots
            int n = fi >> 5, c4 = fi & 31;
            uint32_t d = (uint32_t)__cvta_generic_to_shared(Ws + n * WT_STRIDE + c4 * 4);
            asm volatile("cp.async.cg.shared.global [%0], [%1], 16;"
                         :: "r"(d), "l"(WT + n * 128 + c4 * 4) : "memory");
        }
    };

    // ---- kick off Wq, Wk copies (group 0), overlap with X staging ----
    cpW(WT_rnd[0], Bs0);
    cpW(WT_rnd[1], Bs1);
    CP_COMMIT();

    // ---- stage X tile (128x128 f32 -> tf32, cvt.rna) ----
    #pragma unroll
    for (int i = 0; i < 8; i++) {
        int fi = tid + i * 512;              // 0..4095 float4 slots
        int r = fi >> 5, c4 = fi & 31;
        float4 v = *(const float4*)(x + (size_t)(row0 + r) * 128 + c4 * 4);
        uint4 u; u.x = f2tf(v.x); u.y = f2tf(v.y); u.z = f2tf(v.z); u.w = f2tf(v.w);
        *(uint4*)(Xs + r * XS_STRIDE + c4 * 4) = u;
    }
    if (tid < 128) maskS[tid] = mask[row0 + tid];
    CP_WAIT(0);
    __syncthreads();

    // A ldmatrix bases (two 16-row m-fragments of this warp's 32-row slab)
    const int a_row = wm * 32 + (lane & 15);
    const uint32_t a_base0 =
        (uint32_t)__cvta_generic_to_shared(Xs + a_row * XS_STRIDE + ((lane >> 4) & 1) * 4);
    const uint32_t a_base1 = a_base0 + 16 * XS_STRIDE * 4;

    // B ldmatrix lane offsets: x4 -> matrices {n-frag0 klo, n-frag0 khi, n-frag1 klo, n-frag1 khi}
    const int bn_off = (lane & 7) + ((lane >> 4) << 3);   // n row within 16-n group
    const int bk_off = ((lane >> 3) & 1) * 4;             // k half (0 or 4 words)
    const uint32_t b_row_word = (uint32_t)((wn * 32 + bn_off) * WT_STRIDE + bk_off);

    const int colb = wn * 32 + 2 * tig;       // acc cols (colb, colb+1) + n*8

    // GEMM: acc = Xs(128x128) @ Ws^T; warp tile 32x32; A and B via ldmatrix.x4
    auto gemm = [&](float acc[2][4][4], const uint32_t* Ws) {
        #pragma unroll
        for (int mf = 0; mf < 2; mf++)
            #pragma unroll
            for (int n = 0; n < 4; n++)
                #pragma unroll
                for (int j = 0; j < 4; j++) acc[mf][n][j] = 0.f;
        const uint32_t b_base0 =
            (uint32_t)__cvta_generic_to_shared(Ws + b_row_word);
        const uint32_t b_base1 = b_base0 + 16 * WT_STRIDE * 4;   // n-frags 2,3
        #pragma unroll
        for (int kk = 0; kk < 16; kk++) {
            const uint32_t k0b = (uint32_t)(kk * 8 * 4);         // k0 in bytes
            uint32_t a0[2], a1[2], a2[2], a3[2];
            ldsm_x4(a0[0], a1[0], a2[0], a3[0], a_base0 + k0b);
            ldsm_x4(a0[1], a1[1], a2[1], a3[1], a_base1 + k0b);
            uint32_t b[4][2];
            ldsm_x4(b[0][0], b[0][1], b[1][0], b[1][1], b_base0 + k0b);
            ldsm_x4(b[2][0], b[2][1], b[3][0], b[3][1], b_base1 + k0b);
            #pragma unroll
            for (int mf = 0; mf < 2; mf++)
                #pragma unroll
                for (int n = 0; n < 4; n++)
                    mma_tf32(acc[mf][n], a0[mf], a1[mf], a2[mf], a3[mf],
                             b[n][0], b[n][1]);
        }
    };

    auto bias_add = [&](float acc[2][4][4], const float* __restrict__ bias) {
        #pragma unroll
        for (int n = 0; n < 4; n++) {
            float2 bb = __ldg((const float2*)(bias + colb + n * 8));
            #pragma unroll
            for (int mf = 0; mf < 2; mf++) {
                acc[mf][n][0] += bb.x; acc[mf][n][1] += bb.y;
                acc[mf][n][2] += bb.x; acc[mf][n][3] += bb.y;
            }
        }
    };

    float P[2][2][4];     // attention weights per (mf, half, key atom)
    float rv[2][2];       // residue-valid flag per (mf, half)
    {
        // ---- Q GEMM ----
        float Qa[2][4][4];
        gemm(Qa, Bs0);
        bias_add(Qa, bq);
        __syncthreads();                 // all warps done reading Bs0

        // Wv -> Bs0 flows during K GEMM + softmax (group 1)
        cpW(WT_rnd[2], Bs0);
        CP_COMMIT();

        // ---- K GEMM ----
        float Ka[2][4][4];
        gemm(Ka, Bs1);
        bias_add(Ka, bk);

        // ---- scores + softmax, registers + shuffles ----
        #pragma unroll
        for (int mf = 0; mf < 2; mf++) {
            #pragma unroll
            for (int half = 0; half < 2; half++) {
                const int rowg = wm * 32 + mf * 16 + half * 8 + gid;
                const int rb   = rowg & ~3;
                float vb[4], sc[4];
                #pragma unroll
                for (int e = 0; e < 4; e++)
                    vb[e] = (maskS[rb | e] != 0u) ? 1.f : 0.f;
                #pragma unroll
                for (int e = 0; e < 4; e++) {
                    const int src = (lane & ~12) | (e << 2);
                    float s = 0.f;
                    #pragma unroll
                    for (int n = 0; n < 4; n++) {
                        #pragma unroll
                        for (int dj = 0; dj < 2; dj++) {
                            int j = half * 2 + dj;
                            s = fmaf(Qa[mf][n][j],
                                     __shfl_sync(0xffffffffu, Ka[mf][n][j], src), s);
                        }
                    }
                    s += __shfl_xor_sync(0xffffffffu, s, 1);
                    s += __shfl_xor_sync(0xffffffffu, s, 2);
                    sc[e] = (vb[e] > 0.f) ? s * 0.17677669529663687f : -1e30f;
                }
                float mx = fmaxf(fmaxf(sc[0], sc[1]), fmaxf(sc[2], sc[3]));
                float ps = 0.f, pe[4];
                #pragma unroll
                for (int e = 0; e < 4; e++) {
                    pe[e] = (vb[e] > 0.f) ? __expf(sc[e] - mx) : 0.f;
                    ps += pe[e];
                }
                float any = vb[0] + vb[1] + vb[2] + vb[3];
                float inv = (any > 0.f) ? (1.f / ps) : 0.f;
                rv[mf][half] = (any > 0.f) ? 1.f : 0.f;
                #pragma unroll
                for (int e = 0; e < 4; e++) P[mf][half][e] = pe[e] * inv;
            }
        }
    }   // Qa, Ka dead

    __syncthreads();                 // all warps done reading Bs1 (K GEMM)

    // Wo -> Bs1 flows during V GEMM + P.V + ctx write (group 2)
    cpW(WT_rnd[3], Bs1);
    CP_COMMIT();
    CP_WAIT(1);                      // Wv (group 1) arrived
    __syncthreads();                 // Wv visible to all warps

    // ---- V GEMM + P·V (registers) ----
    float cx[2][4][4];
    {
        float Va[2][4][4];
        gemm(Va, Bs0);
        bias_add(Va, bv);
        #pragma unroll
        for (int mf = 0; mf < 2; mf++)
            #pragma unroll
            for (int n = 0; n < 4; n++)
                #pragma unroll
                for (int j = 0; j < 4; j++) cx[mf][n][j] = 0.f;
        #pragma unroll
        for (int mf = 0; mf < 2; mf++) {
            #pragma unroll
            for (int half = 0; half < 2; half++) {
                #pragma unroll
                for (int e = 0; e < 4; e++) {
                    const int src = (lane & ~12) | (e << 2);
                    const float pw = P[mf][half][e];
                    #pragma unroll
                    for (int n = 0; n < 4; n++) {
                        #pragma unroll
                        for (int dj = 0; dj < 2; dj++) {
                            int j = half * 2 + dj;
                            cx[mf][n][j] = fmaf(pw,
                                __shfl_sync(0xffffffffu, Va[mf][n][j], src),
                                cx[mf][n][j]);
                        }
                    }
                }
            }
        }
    }   // Va dead

    __syncthreads();            // all warps done reading Xs (V GEMM)

    // ---- ctx -> Xs (tf32, cvt.rna) ----
    #pragma unroll
    for (int mf = 0; mf < 2; mf++) {
        #pragma unroll
        for (int half = 0; half < 2; half++) {
            const int rowg = wm * 32 + mf * 16 + half * 8 + gid;
            #pragma unroll
            for (int n = 0; n < 4; n++) {
                uint2 u;
                u.x = f2tf(cx[mf][n][half * 2 + 0]);
                u.y = f2tf(cx[mf][n][half * 2 + 1]);
                *(uint2*)(Xs + rowg * XS_STRIDE + colb + n * 8) = u;
            }
        }
    }
    CP_WAIT(0);                 // Wo (group 2) arrived
    __syncthreads();            // ctx + Wo visible

    // ---- O GEMM + bias + residue zeroing -> global ----
    {
        float Oa[2][4][4];
        gemm(Oa, Bs1);
        bias_add(Oa, bo);
        #pragma unroll
        for (int mf = 0; mf < 2; mf++) {
            #pragma unroll
            for (int half = 0; half < 2; half++) {
                const int rowg = wm * 32 + mf * 16 + half * 8 + gid;
                const float r = rv[mf][half];
                #pragma unroll
                for (int n = 0; n < 4; n++) {
                    float2 o;
                    o.x = Oa[mf][n][half * 2 + 0] * r;
                    o.y = Oa[mf][n][half * 2 + 1] * r;
                    *(float2*)(out + (size_t)(row0 + rowg) * 128 + colb + n * 8) = o;
                }
            }
        }
    }
}

extern "C" void kernel_launch(void* const* d_in, const int* in_sizes, int n_in,
                              void* d_out, int out_size)
{
    const float*    x    = (const float*)d_in[0];
    const uint32_t* mask = (const uint32_t*)d_in[1];
    const float*    Wq   = (const float*)d_in[2];
    const float*    bq   = (const float*)d_in[3];
    const float*    Wk   = (const float*)d_in[4];
    const float*    bk   = (const float*)d_in[5];
    const float*    Wv   = (const float*)d_in[6];
    const float*    bv   = (const float*)d_in[7];
    const float*    Wo   = (const float*)d_in[8];
    const float*    bo   = (const float*)d_in[9];
    float* out = (float*)d_out;

    const int rows = in_sizes[0] / 128;   // 131072
    const int grid = rows / 128;          // 1024

    prep_kernel<<<16, 256>>>(Wq, Wk, Wv, Wo);

    cudaFuncSetAttribute(laa_kernel, cudaFuncAttributeMaxDynamicSharedMemorySize, SMEM_BYTES);
    laa_kernel<<<grid, 512, SMEM_BYTES>>>(x, mask, bq, bk, bv, bo, out);
}

// round 14
// speedup vs baseline: 1.1227x; 1.0748x over previous
#include <cuda_runtime.h>
#include <cstdint>

#define XS_STRIDE 132   // words: 128 + 4 pad — conflict-free ldmatrix
#define WS_STRIDE 136   // words: 128 + 8 pad — conflict-free scalar B loads

// smem byte offsets
#define OFF_A   0         // X tile / ctx: 128 x 132 tf32 words (67584 B)
#define OFF_B0  67584     // W buffer 0:   128 x 136 words (69632 B)
#define OFF_B1  137216    // W buffer 1:   128 x 136 words (69632 B)
#define OFF_MS  206848    // 128 mask words (512 B)
#define SMEM_BYTES 207360

static __device__ __forceinline__ uint32_t f2tf(float f) {
    uint32_t r; asm("cvt.rna.tf32.f32 %0, %1;" : "=r"(r) : "f"(f)); return r;
}

static __device__ __forceinline__ void mma_tf32(float* d,
        uint32_t a0, uint32_t a1, uint32_t a2, uint32_t a3,
        uint32_t b0, uint32_t b1) {
    asm volatile(
        "mma.sync.aligned.m16n8k8.row.col.f32.tf32.tf32.f32 "
        "{%0,%1,%2,%3}, {%4,%5,%6,%7}, {%8,%9}, {%0,%1,%2,%3};\n"
        : "+f"(d[0]), "+f"(d[1]), "+f"(d[2]), "+f"(d[3])
        : "r"(a0), "r"(a1), "r"(a2), "r"(a3), "r"(b0), "r"(b1));
}

static __device__ __forceinline__ void ldsm_x4(uint32_t& r0, uint32_t& r1,
        uint32_t& r2, uint32_t& r3, uint32_t saddr) {
    asm volatile("ldmatrix.sync.aligned.m8n8.x4.shared.b16 {%0,%1,%2,%3}, [%4];"
                 : "=r"(r0), "=r"(r1), "=r"(r2), "=r"(r3) : "r"(saddr));
}

#define CP_COMMIT()  asm volatile("cp.async.commit_group;" ::: "memory")
#define CP_WAIT(n)   asm volatile("cp.async.wait_group %0;" :: "n"(n) : "memory")

__global__ __launch_bounds__(512, 1)
void laa_kernel(const float* __restrict__ x, const uint32_t* __restrict__ mask,
                const float* __restrict__ Wq, const float* __restrict__ bq,
                const float* __restrict__ Wk, const float* __restrict__ bk,
                const float* __restrict__ Wv, const float* __restrict__ bv,
                const float* __restrict__ Wo, const float* __restrict__ bo,
                float* __restrict__ out)
{
    extern __shared__ char smem[];
    uint32_t* Xs    = (uint32_t*)(smem + OFF_A);
    uint32_t* Bs0   = (uint32_t*)(smem + OFF_B0);
    uint32_t* Bs1   = (uint32_t*)(smem + OFF_B1);
    uint32_t* maskS = (uint32_t*)(smem + OFF_MS);

    const int tid  = threadIdx.x;
    const int lane = tid & 31;
    const int w    = tid >> 5;     // 0..15
    const int gid  = lane >> 2;    // 0..7
    const int tig  = lane & 3;     // 0..3
    const int wm   = w >> 2;       // row group: rows 32*wm..
    const int wn   = w & 3;        // col slab = head wn
    const int row0 = blockIdx.x * 128;

    // async W copy: raw f32 (HMMA reads tf32 bits; deterministic inputs, verified)
    auto cpW = [&](const float* __restrict__ W, uint32_t* Ws) {
        #pragma unroll
        for (int i = 0; i < 8; i++) {
            int fi = tid + i * 512;          // 0..4095 float4 slots
            int r = fi >> 5, c4 = fi & 31;
            uint32_t d = (uint32_t)__cvta_generic_to_shared(Ws + r * WS_STRIDE + c4 * 4);
            asm volatile("cp.async.cg.shared.global [%0], [%1], 16;"
                         :: "r"(d), "l"(W + r * 128 + c4 * 4) : "memory");
        }
    };

    // ---- issue X LDGs first (longest-latency loads lead the queue) ----
    float4 xv[8];
    #pragma unroll
    for (int i = 0; i < 8; i++) {
        int fi = tid + i * 512;              // 0..4095 float4 slots
        int r = fi >> 5, c4 = fi & 31;
        xv[i] = *(const float4*)(x + (size_t)(row0 + r) * 128 + c4 * 4);
    }

    // ---- Wq (group 0), Wk (group 1) as separate cp groups ----
    cpW(Wq, Bs0);
    CP_COMMIT();
    cpW(Wk, Bs1);
    CP_COMMIT();

    // ---- convert + store X tile (f32 -> tf32, cvt.rna) ----
    #pragma unroll
    for (int i = 0; i < 8; i++) {
        int fi = tid + i * 512;
        int r = fi >> 5, c4 = fi & 31;
        uint4 u;
        u.x = f2tf(xv[i].x); u.y = f2tf(xv[i].y);
        u.z = f2tf(xv[i].z); u.w = f2tf(xv[i].w);
        *(uint4*)(Xs + r * XS_STRIDE + c4 * 4) = u;
    }
    if (tid < 128) maskS[tid] = mask[row0 + tid];
    CP_WAIT(1);                 // Wq arrived (Wk may still be in flight)
    __syncthreads();

    // ldmatrix bases for the two 16-row m-fragments of this warp's 32-row slab
    const int a_row = wm * 32 + (lane & 15);
    const uint32_t a_base0 =
        (uint32_t)__cvta_generic_to_shared(Xs + a_row * XS_STRIDE + ((lane >> 4) & 1) * 4);
    const uint32_t a_base1 = a_base0 + 16 * XS_STRIDE * 4;

    const int colb = wn * 32 + 2 * tig;       // acc cols (colb, colb+1) + n*8

    // GEMM: acc = Xs(128x128) @ Ws(128x128); warp tile 32x32 (R8-proven)
    auto gemm = [&](float acc[2][4][4], const uint32_t* Ws) {
        #pragma unroll
        for (int mf = 0; mf < 2; mf++)
            #pragma unroll
            for (int n = 0; n < 4; n++)
                #pragma unroll
                for (int j = 0; j < 4; j++) acc[mf][n][j] = 0.f;
        #pragma unroll
        for (int kk = 0; kk < 16; kk++) {
            const int k0 = kk * 8;
            uint32_t a0[2], a1[2], a2[2], a3[2];
            ldsm_x4(a0[0], a1[0], a2[0], a3[0], a_base0 + (uint32_t)(k0 * 4));
            ldsm_x4(a0[1], a1[1], a2[1], a3[1], a_base1 + (uint32_t)(k0 * 4));
            const uint32_t* bp = Ws + (k0 + tig) * WS_STRIDE + wn * 32 + gid;
            uint32_t b[4][2];
            #pragma unroll
            for (int n = 0; n < 4; n++) {
                b[n][0] = bp[n * 8];
                b[n][1] = bp[4 * WS_STRIDE + n * 8];
            }
            #pragma unroll
            for (int mf = 0; mf < 2; mf++)
                #pragma unroll
                for (int n = 0; n < 4; n++)
                    mma_tf32(acc[mf][n], a0[mf], a1[mf], a2[mf], a3[mf],
                             b[n][0], b[n][1]);
        }
    };

    auto bias_add = [&](float acc[2][4][4], const float* __restrict__ bias) {
        #pragma unroll
        for (int n = 0; n < 4; n++) {
            float2 bb = __ldg((const float2*)(bias + colb + n * 8));
            #pragma unroll
            for (int mf = 0; mf < 2; mf++) {
                acc[mf][n][0] += bb.x; acc[mf][n][1] += bb.y;
                acc[mf][n][2] += bb.x; acc[mf][n][3] += bb.y;
            }
        }
    };

    float P[2][2][4];     // attention weights per (mf, half, key atom)
    float rv[2][2];       // residue-valid flag per (mf, half)
    {
        // ---- Q GEMM (only Wq needed; Wk still streaming) ----
        float Qa[2][4][4];
        gemm(Qa, Bs0);
        bias_add(Qa, bq);
        __syncthreads();                 // all warps done reading Bs0

        // Wv -> Bs0 (group 2) flows during K GEMM + softmax
        cpW(Wv, Bs0);
        CP_COMMIT();
        CP_WAIT(1);                      // Wk (group 1) arrived; Wv may pend
        __syncthreads();                 // Wk visible to all warps

        // ---- K GEMM ----
        float Ka[2][4][4];
        gemm(Ka, Bs1);
        bias_add(Ka, bk);

        // ---- scores + softmax, registers + shuffles ----
        #pragma unroll
        for (int mf = 0; mf < 2; mf++) {
            #pragma unroll
            for (int half = 0; half < 2; half++) {
                const int rowg = wm * 32 + mf * 16 + half * 8 + gid;
                const int rb   = rowg & ~3;
                float vb[4], sc[4];
                #pragma unroll
                for (int e = 0; e < 4; e++)
                    vb[e] = (maskS[rb | e] != 0u) ? 1.f : 0.f;
                #pragma unroll
                for (int e = 0; e < 4; e++) {
                    const int src = (lane & ~12) | (e << 2);
                    float s = 0.f;
                    #pragma unroll
                    for (int n = 0; n < 4; n++) {
                        #pragma unroll
                        for (int dj = 0; dj < 2; dj++) {
                            int j = half * 2 + dj;
                            s = fmaf(Qa[mf][n][j],
                                     __shfl_sync(0xffffffffu, Ka[mf][n][j], src), s);
                        }
                    }
                    s += __shfl_xor_sync(0xffffffffu, s, 1);
                    s += __shfl_xor_sync(0xffffffffu, s, 2);
                    sc[e] = (vb[e] > 0.f) ? s * 0.17677669529663687f : -1e30f;
                }
                float mx = fmaxf(fmaxf(sc[0], sc[1]), fmaxf(sc[2], sc[3]));
                float ps = 0.f, pe[4];
                #pragma unroll
                for (int e = 0; e < 4; e++) {
                    pe[e] = (vb[e] > 0.f) ? __expf(sc[e] - mx) : 0.f;
                    ps += pe[e];
                }
                float any = vb[0] + vb[1] + vb[2] + vb[3];
                float inv = (any > 0.f) ? (1.f / ps) : 0.f;
                rv[mf][half] = (any > 0.f) ? 1.f : 0.f;
                #pragma unroll
                for (int e = 0; e < 4; e++) P[mf][half][e] = pe[e] * inv;
            }
        }
    }   // Qa, Ka dead

    __syncthreads();                 // all warps done reading Bs1 (K GEMM)

    // Wo -> Bs1 (group 3) flows during V GEMM + P.V + ctx write
    cpW(Wo, Bs1);
    CP_COMMIT();
    CP_WAIT(1);                      // Wv (group 2) arrived
    __syncthreads();                 // Wv visible to all warps

    // ---- V GEMM + P·V (registers) ----
    float cx[2][4][4];
    {
        float Va[2][4][4];
        gemm(Va, Bs0);
        bias_add(Va, bv);
        #pragma unroll
        for (int mf = 0; mf < 2; mf++)
            #pragma unroll
            for (int n = 0; n < 4; n++)
                #pragma unroll
                for (int j = 0; j < 4; j++) cx[mf][n][j] = 0.f;
        #pragma unroll
        for (int mf = 0; mf < 2; mf++) {
            #pragma unroll
            for (int half = 0; half < 2; half++) {
                #pragma unroll
                for (int e = 0; e < 4; e++) {
                    const int src = (lane & ~12) | (e << 2);
                    const float pw = P[mf][half][e];
                    #pragma unroll
                    for (int n = 0; n < 4; n++) {
                        #pragma unroll
                        for (int dj = 0; dj < 2; dj++) {
                            int j = half * 2 + dj;
                            cx[mf][n][j] = fmaf(pw,
                                __shfl_sync(0xffffffffu, Va[mf][n][j], src),
                                cx[mf][n][j]);
                        }
                    }
                }
            }
        }
    }   // Va dead

    __syncthreads();            // all warps done reading Xs (V GEMM)

    // ---- ctx -> Xs (tf32, cvt.rna) ----
    #pragma unroll
    for (int mf = 0; mf < 2; mf++) {
        #pragma unroll
        for (int half = 0; half < 2; half++) {
            const int rowg = wm * 32 + mf * 16 + half * 8 + gid;
            #pragma unroll
            for (int n = 0; n < 4; n++) {
                uint2 u;
                u.x = f2tf(cx[mf][n][half * 2 + 0]);
                u.y = f2tf(cx[mf][n][half * 2 + 1]);
                *(uint2*)(Xs + rowg * XS_STRIDE + colb + n * 8) = u;
            }
        }
    }
    CP_WAIT(0);                 // Wo (group 3) arrived
    __syncthreads();            // ctx + Wo visible

    // ---- O GEMM + bias + residue zeroing -> global ----
    {
        float Oa[2][4][4];
        gemm(Oa, Bs1);
        bias_add(Oa, bo);
        #pragma unroll
        for (int mf = 0; mf < 2; mf++) {
            #pragma unroll
            for (int half = 0; half < 2; half++) {
                const int rowg = wm * 32 + mf * 16 + half * 8 + gid;
                const float r = rv[mf][half];
                #pragma unroll
                for (int n = 0; n < 4; n++) {
                    float2 o;
                    o.x = Oa[mf][n][half * 2 + 0] * r;
                    o.y = Oa[mf][n][half * 2 + 1] * r;
                    *(float2*)(out + (size_t)(row0 + rowg) * 128 + colb + n * 8) = o;
                }
            }
        }
    }
}

extern "C" void kernel_launch(void* const* d_in, const int* in_sizes, int n_in,
                              void* d_out, int out_size)
{
    const float*    x    = (const float*)d_in[0];
    const uint32_t* mask = (const uint32_t*)d_in[1];
    const float*    Wq   = (const float*)d_in[2];
    const float*    bq   = (const float*)d_in[3];
    const float*    Wk   = (const float*)d_in[4];
    const float*    bk   = (const float*)d_in[5];
    const float*    Wv   = (const float*)d_in[6];
    const float*    bv   = (const float*)d_in[7];
    const float*    Wo   = (const float*)d_in[8];
    const float*    bo   = (const float*)d_in[9];
    float* out = (float*)d_out;

    const int rows = in_sizes[0] / 128;   // 131072
    const int grid = rows / 128;          // 1024

    cudaFuncSetAttribute(laa_kernel, cudaFuncAttributeMaxDynamicSharedMemorySize, SMEM_BYTES);
    laa_kernel<<<grid, 512, SMEM_BYTES>>>(x, mask, Wq, bq, Wk, bk, Wv, bv, Wo, bo, out);
}

// round 15
// speedup vs baseline: 1.1500x; 1.0243x over previous
#include <cuda_runtime.h>
#include <cstdint>

#define XS_STRIDE 132   // words: 128 + 4 pad — conflict-free ldmatrix (A)

// smem byte offsets
#define OFF_A   0         // X tile / ctx: 128 x 132 tf32 words (67584 B)
#define OFF_B0  67584     // W packed buffer 0: 16384 words (65536 B)
#define OFF_B1  133120    // W packed buffer 1: 16384 words (65536 B)
#define OFF_MS  198656    // 128 mask words (512 B)
#define SMEM_BYTES 199168

// pre-rounded (tf32, rna) RE-LAYOUTED weights:
// WP[g][(k>>3)*1024 + c*8 + 2*(k&3) + ((k>>2)&1)] = rna(W[g][k][c])
__device__ float WP_rnd[4][16384];

static __device__ __forceinline__ uint32_t f2tf(float f) {
    uint32_t r; asm("cvt.rna.tf32.f32 %0, %1;" : "=r"(r) : "f"(f)); return r;
}

static __device__ __forceinline__ void mma_tf32(float* d,
        uint32_t a0, uint32_t a1, uint32_t a2, uint32_t a3,
        uint32_t b0, uint32_t b1) {
    asm volatile(
        "mma.sync.aligned.m16n8k8.row.col.f32.tf32.tf32.f32 "
        "{%0,%1,%2,%3}, {%4,%5,%6,%7}, {%8,%9}, {%0,%1,%2,%3};\n"
        : "+f"(d[0]), "+f"(d[1]), "+f"(d[2]), "+f"(d[3])
        : "r"(a0), "r"(a1), "r"(a2), "r"(a3), "r"(b0), "r"(b1));
}

static __device__ __forceinline__ void ldsm_x4(uint32_t& r0, uint32_t& r1,
        uint32_t& r2, uint32_t& r3, uint32_t saddr) {
    asm volatile("ldmatrix.sync.aligned.m8n8.x4.shared.b16 {%0,%1,%2,%3}, [%4];"
                 : "=r"(r0), "=r"(r1), "=r"(r2), "=r"(r3) : "r"(saddr));
}

#define CP_COMMIT()  asm volatile("cp.async.commit_group;" ::: "memory")
#define CP_WAIT(n)   asm volatile("cp.async.wait_group %0;" :: "n"(n) : "memory")

// ---- prep: tf32(rna) + relayout: inner-8 = k-pairs (tig, tig+4) adjacent ----
__global__ void prep_kernel(const float* __restrict__ Wq, const float* __restrict__ Wk,
                            const float* __restrict__ Wv, const float* __restrict__ Wo)
{
    const int t = blockIdx.x * blockDim.x + threadIdx.x;   // 0..4095
    const float* src[4] = {Wq, Wk, Wv, Wo};
    #pragma unroll
    for (int g = 0; g < 4; g++) {
        #pragma unroll
        for (int i = 0; i < 4; i++) {
            int idx = t + i * 4096;        // 0..16383 = k*128 + c
            int k = idx >> 7;
            int c = idx & 127;
            uint32_t v = f2tf(src[g][idx]);
            int dst = ((k >> 3) << 10) + (c << 3) + 2 * (k & 3) + ((k >> 2) & 1);
            WP_rnd[g][dst] = __uint_as_float(v);
        }
    }
}

__global__ __launch_bounds__(512, 1)
void laa_kernel(const float* __restrict__ x, const uint32_t* __restrict__ mask,
                const float* __restrict__ bq, const float* __restrict__ bk,
                const float* __restrict__ bv, const float* __restrict__ bo,
                float* __restrict__ out)
{
    extern __shared__ char smem[];
    uint32_t* Xs    = (uint32_t*)(smem + OFF_A);
    uint32_t* Bs0   = (uint32_t*)(smem + OFF_B0);
    uint32_t* Bs1   = (uint32_t*)(smem + OFF_B1);
    uint32_t* maskS = (uint32_t*)(smem + OFF_MS);

    const int tid  = threadIdx.x;
    const int lane = tid & 31;
    const int w    = tid >> 5;     // 0..15
    const int gid  = lane >> 2;    // 0..7
    const int tig  = lane & 3;     // 0..3
    const int wm   = w >> 2;       // row group: rows 32*wm..
    const int wn   = w & 3;        // col slab = head wn
    const int row0 = blockIdx.x * 128;

    // async W copy: pure linear 64KB (already rounded + relayouted)
    auto cpW = [&](const float* __restrict__ WPg, uint32_t* Ws) {
        #pragma unroll
        for (int i = 0; i < 8; i++) {
            int fi = tid + i * 512;          // 0..4095 float4 slots
            uint32_t d = (uint32_t)__cvta_generic_to_shared(Ws + fi * 4);
            asm volatile("cp.async.cg.shared.global [%0], [%1], 16;"
                         :: "r"(d), "l"(WPg + fi * 4) : "memory");
        }
    };

    // ---- issue X LDGs first (longest-latency loads lead the queue) ----
    float4 xv[8];
    #pragma unroll
    for (int i = 0; i < 8; i++) {
        int fi = tid + i * 512;              // 0..4095 float4 slots
        int r = fi >> 5, c4 = fi & 31;
        xv[i] = *(const float4*)(x + (size_t)(row0 + r) * 128 + c4 * 4);
    }

    // ---- Wq (group 0), Wk (group 1) ----
    cpW(WP_rnd[0], Bs0);
    CP_COMMIT();
    cpW(WP_rnd[1], Bs1);
    CP_COMMIT();

    // ---- convert + store X tile (f32 -> tf32, cvt.rna) ----
    #pragma unroll
    for (int i = 0; i < 8; i++) {
        int fi = tid + i * 512;
        int r = fi >> 5, c4 = fi & 31;
        uint4 u;
        u.x = f2tf(xv[i].x); u.y = f2tf(xv[i].y);
        u.z = f2tf(xv[i].z); u.w = f2tf(xv[i].w);
        *(uint4*)(Xs + r * XS_STRIDE + c4 * 4) = u;
    }
    if (tid < 128) maskS[tid] = mask[row0 + tid];
    CP_WAIT(1);                 // Wq arrived (Wk may still be in flight)
    __syncthreads();

    // A ldmatrix bases (two 16-row m-fragments of this warp's 32-row slab)
    const int a_row = wm * 32 + (lane & 15);
    const uint32_t a_base0 =
        (uint32_t)__cvta_generic_to_shared(Xs + a_row * XS_STRIDE + ((lane >> 4) & 1) * 4);
    const uint32_t a_base1 = a_base0 + 16 * XS_STRIDE * 4;

    // B packed-layout per-thread word offset: col = wn*32+gid (+8 per n-frag)
    const uint32_t b_off = (uint32_t)(((wn * 32 + gid) << 3) + 2 * tig);

    const int colb = wn * 32 + 2 * tig;       // acc cols (colb, colb+1) + n*8

    // GEMM: acc = Xs(128x128) @ W; warp tile 32x32; B via LDS.64 pairs
    auto gemm = [&](float acc[2][4][4], const uint32_t* Ws) {
        #pragma unroll
        for (int mf = 0; mf < 2; mf++)
            #pragma unroll
            for (int n = 0; n < 4; n++)
                #pragma unroll
                for (int j = 0; j < 4; j++) acc[mf][n][j] = 0.f;
        const uint32_t* bbase = Ws + b_off;
        #pragma unroll
        for (int kk = 0; kk < 16; kk++) {
            const int k0 = kk * 8;
            uint32_t a0[2], a1[2], a2[2], a3[2];
            ldsm_x4(a0[0], a1[0], a2[0], a3[0], a_base0 + (uint32_t)(k0 * 4));
            ldsm_x4(a0[1], a1[1], a2[1], a3[1], a_base1 + (uint32_t)(k0 * 4));
            const uint32_t* bp = bbase + (kk << 10);
            uint2 b[4];
            #pragma unroll
            for (int n = 0; n < 4; n++)
                b[n] = *(const uint2*)(bp + (n << 6));
            #pragma unroll
            for (int mf = 0; mf < 2; mf++)
                #pragma unroll
                for (int n = 0; n < 4; n++)
                    mma_tf32(acc[mf][n], a0[mf], a1[mf], a2[mf], a3[mf],
                             b[n].x, b[n].y);
        }
    };

    auto bias_add = [&](float acc[2][4][4], const float* __restrict__ bias) {
        #pragma unroll
        for (int n = 0; n < 4; n++) {
            float2 bb = __ldg((const float2*)(bias + colb + n * 8));
            #pragma unroll
            for (int mf = 0; mf < 2; mf++) {
                acc[mf][n][0] += bb.x; acc[mf][n][1] += bb.y;
                acc[mf][n][2] += bb.x; acc[mf][n][3] += bb.y;
            }
        }
    };

    float P[2][2][4];     // attention weights per (mf, half, key atom)
    float rv[2][2];       // residue-valid flag per (mf, half)
    {
        // ---- Q GEMM (only Wq needed; Wk still streaming) ----
        float Qa[2][4][4];
        gemm(Qa, Bs0);
        bias_add(Qa, bq);
        __syncthreads();                 // all warps done reading Bs0

        // Wv -> Bs0 (group 2) flows during K GEMM + softmax
        cpW(WP_rnd[2], Bs0);
        CP_COMMIT();
        CP_WAIT(1);                      // Wk (group 1) arrived; Wv may pend
        __syncthreads();                 // Wk visible to all warps

        // ---- K GEMM ----
        float Ka[2][4][4];
        gemm(Ka, Bs1);
        bias_add(Ka, bk);

        // ---- scores + softmax, registers + shuffles ----
        #pragma unroll
        for (int mf = 0; mf < 2; mf++) {
            #pragma unroll
            for (int half = 0; half < 2; half++) {
                const int rowg = wm * 32 + mf * 16 + half * 8 + gid;
                const int rb   = rowg & ~3;
                float vb[4], sc[4];
                #pragma unroll
                for (int e = 0; e < 4; e++)
                    vb[e] = (maskS[rb | e] != 0u) ? 1.f : 0.f;
                #pragma unroll
                for (int e = 0; e < 4; e++) {
                    const int src = (lane & ~12) | (e << 2);
                    float s = 0.f;
                    #pragma unroll
                    for (int n = 0; n < 4; n++) {
                        #pragma unroll
                        for (int dj = 0; dj < 2; dj++) {
                            int j = half * 2 + dj;
                            s = fmaf(Qa[mf][n][j],
                                     __shfl_sync(0xffffffffu, Ka[mf][n][j], src), s);
                        }
                    }
                    s += __shfl_xor_sync(0xffffffffu, s, 1);
                    s += __shfl_xor_sync(0xffffffffu, s, 2);
                    sc[e] = (vb[e] > 0.f) ? s * 0.17677669529663687f : -1e30f;
                }
                float mx = fmaxf(fmaxf(sc[0], sc[1]), fmaxf(sc[2], sc[3]));
                float ps = 0.f, pe[4];
                #pragma unroll
                for (int e = 0; e < 4; e++) {
                    pe[e] = (vb[e] > 0.f) ? __expf(sc[e] - mx) : 0.f;
                    ps += pe[e];
                }
                float any = vb[0] + vb[1] + vb[2] + vb[3];
                float inv = (any > 0.f) ? (1.f / ps) : 0.f;
                rv[mf][half] = (any > 0.f) ? 1.f : 0.f;
                #pragma unroll
                for (int e = 0; e < 4; e++) P[mf][half][e] = pe[e] * inv;
            }
        }
    }   // Qa, Ka dead

    __syncthreads();                 // all warps done reading Bs1 (K GEMM)

    // Wo -> Bs1 (group 3) flows during V GEMM + P.V + ctx write
    cpW(WP_rnd[3], Bs1);
    CP_COMMIT();
    CP_WAIT(1);                      // Wv (group 2) arrived
    __syncthreads();                 // Wv visible to all warps

    // ---- V GEMM + P·V (registers) ----
    float cx[2][4][4];
    {
        float Va[2][4][4];
        gemm(Va, Bs0);
        bias_add(Va, bv);
        #pragma unroll
        for (int mf = 0; mf < 2; mf++)
            #pragma unroll
            for (int n = 0; n < 4; n++)
                #pragma unroll
                for (int j = 0; j < 4; j++) cx[mf][n][j] = 0.f;
        #pragma unroll
        for (int mf = 0; mf < 2; mf++) {
            #pragma unroll
            for (int half = 0; half < 2; half++) {
                #pragma unroll
                for (int e = 0; e < 4; e++) {
                    const int src = (lane & ~12) | (e << 2);
                    const float pw = P[mf][half][e];
                    #pragma unroll
                    for (int n = 0; n < 4; n++) {
                        #pragma unroll
                        for (int dj = 0; dj < 2; dj++) {
                            int j = half * 2 + dj;
                            cx[mf][n][j] = fmaf(pw,
                                __shfl_sync(0xffffffffu, Va[mf][n][j], src),
                                cx[mf][n][j]);
                        }
                    }
                }
            }
        }
    }   // Va dead

    __syncthreads();            // all warps done reading Xs (V GEMM)

    // ---- ctx -> Xs (tf32, cvt.rna) ----
    #pragma unroll
    for (int mf = 0; mf < 2; mf++) {
        #pragma unroll
        for (int half = 0; half < 2; half++) {
            const int rowg = wm * 32 + mf * 16 + half * 8 + gid;
            #pragma unroll
            for (int n = 0; n < 4; n++) {
                uint2 u;
                u.x = f2tf(cx[mf][n][half * 2 + 0]);
                u.y = f2tf(cx[mf][n][half * 2 + 1]);
                *(uint2*)(Xs + rowg * XS_STRIDE + colb + n * 8) = u;
            }
        }
    }
    CP_WAIT(0);                 // Wo (group 3) arrived
    __syncthreads();            // ctx + Wo visible

    // ---- O GEMM + bias + residue zeroing -> global ----
    {
        float Oa[2][4][4];
        gemm(Oa, Bs1);
        bias_add(Oa, bo);
        #pragma unroll
        for (int mf = 0; mf < 2; mf++) {
            #pragma unroll
            for (int half = 0; half < 2; half++) {
                const int rowg = wm * 32 + mf * 16 + half * 8 + gid;
                const float r = rv[mf][half];
                #pragma unroll
                for (int n = 0; n < 4; n++) {
                    float2 o;
                    o.x = Oa[mf][n][half * 2 + 0] * r;
                    o.y = Oa[mf][n][half * 2 + 1] * r;
                    *(float2*)(out + (size_t)(row0 + rowg) * 128 + colb + n * 8) = o;
                }
            }
        }
    }
}

extern "C" void kernel_launch(void* const* d_in, const int* in_sizes, int n_in,
                              void* d_out, int out_size)
{
    const float*    x    = (const float*)d_in[0];
    const uint32_t* mask = (const uint32_t*)d_in[1];
    const float*    Wq   = (const float*)d_in[2];
    const float*    bq   = (const float*)d_in[3];
    const float*    Wk   = (const float*)d_in[4];
    const float*    bk   = (const float*)d_in[5];
    const float*    Wv   = (const float*)d_in[6];
    const float*    bv   = (const float*)d_in[7];
    const float*    Wo   = (const float*)d_in[8];
    const float*    bo   = (const float*)d_in[9];
    float* out = (float*)d_out;

    const int rows = in_sizes[0] / 128;   // 131072
    const int grid = rows / 128;          // 1024

    prep_kernel<<<16, 256>>>(Wq, Wk, Wv, Wo);

    cudaFuncSetAttribute(laa_kernel, cudaFuncAttributeMaxDynamicSharedMemorySize, SMEM_BYTES);
    laa_kernel<<<grid, 512, SMEM_BYTES>>>(x, mask, bq, bk, bv, bo, out);
}

// round 16
// speedup vs baseline: 1.1666x; 1.0144x over previous
#include <cuda_runtime.h>
#include <cstdint>

#define XS_STRIDE 132   // words: 128 + 4 pad — conflict-free ldmatrix (A)

// smem byte offsets
#define OFF_A   0         // X tile / ctx: 128 x 132 tf32 words (67584 B)
#define OFF_B0  67584     // W packed buffer 0: 16384 words (65536 B)
#define OFF_B1  133120    // W packed buffer 1: 16384 words (65536 B)
#define OFF_MS  198656    // 128 mask words (512 B)
#define SMEM_BYTES 199168

// pre-rounded (tf32, rna) RE-LAYOUTED weights:
// WP[g][(k>>3)*1024 + c*8 + 2*(k&3) + ((k>>2)&1)] = rna(W[g][k][c])
__device__ float WP_rnd[4][16384];

static __device__ __forceinline__ uint32_t f2tf(float f) {
    uint32_t r; asm("cvt.rna.tf32.f32 %0, %1;" : "=r"(r) : "f"(f)); return r;
}

static __device__ __forceinline__ void mma_tf32(float* d,
        uint32_t a0, uint32_t a1, uint32_t a2, uint32_t a3,
        uint32_t b0, uint32_t b1) {
    asm volatile(
        "mma.sync.aligned.m16n8k8.row.col.f32.tf32.tf32.f32 "
        "{%0,%1,%2,%3}, {%4,%5,%6,%7}, {%8,%9}, {%0,%1,%2,%3};\n"
        : "+f"(d[0]), "+f"(d[1]), "+f"(d[2]), "+f"(d[3])
        : "r"(a0), "r"(a1), "r"(a2), "r"(a3), "r"(b0), "r"(b1));
}

static __device__ __forceinline__ void ldsm_x4(uint32_t& r0, uint32_t& r1,
        uint32_t& r2, uint32_t& r3, uint32_t saddr) {
    asm volatile("ldmatrix.sync.aligned.m8n8.x4.shared.b16 {%0,%1,%2,%3}, [%4];"
                 : "=r"(r0), "=r"(r1), "=r"(r2), "=r"(r3) : "r"(saddr));
}

#define CP_COMMIT()  asm volatile("cp.async.commit_group;" ::: "memory")
#define CP_WAIT(n)   asm volatile("cp.async.wait_group %0;" :: "n"(n) : "memory")

// ---- prep: tf32(rna) + relayout, fully coalesced ----
// thread = (g, kg, c): reads W[g][(kg*8+j)*128 + c] (each LDG coalesced over c),
// permutes in registers, writes 2 x STG.128 at WP[g][kg*1024 + c*8].
__global__ void prep_kernel(const float* __restrict__ Wq, const float* __restrict__ Wk,
                            const float* __restrict__ Wv, const float* __restrict__ Wo)
{
    const int t  = blockIdx.x * blockDim.x + threadIdx.x;  // 0..8191
    const int c  = t & 127;          // column (contiguous across threads)
    const int kg = (t >> 7) & 15;    // k-group
    const int g  = t >> 11;          // matrix
    const float* src[4] = {Wq, Wk, Wv, Wo};
    const float* W = src[g];

    float v[8];
    #pragma unroll
    for (int j = 0; j < 8; j++)
        v[j] = W[(kg * 8 + j) * 128 + c];

    // perm: word w holds j = (w&1)*4 + (w>>1)
    uint4 u0, u1;
    u0.x = f2tf(v[0]); u0.y = f2tf(v[4]); u0.z = f2tf(v[1]); u0.w = f2tf(v[5]);
    u1.x = f2tf(v[2]); u1.y = f2tf(v[6]); u1.z = f2tf(v[3]); u1.w = f2tf(v[7]);
    uint32_t* dst = (uint32_t*)&WP_rnd[g][kg * 1024 + c * 8];
    *(uint4*)(dst)     = u0;
    *(uint4*)(dst + 4) = u1;
}

__global__ __launch_bounds__(512, 1)
void laa_kernel(const float* __restrict__ x, const uint32_t* __restrict__ mask,
                const float* __restrict__ bq, const float* __restrict__ bk,
                const float* __restrict__ bv, const float* __restrict__ bo,
                float* __restrict__ out)
{
    extern __shared__ char smem[];
    uint32_t* Xs    = (uint32_t*)(smem + OFF_A);
    uint32_t* Bs0   = (uint32_t*)(smem + OFF_B0);
    uint32_t* Bs1   = (uint32_t*)(smem + OFF_B1);
    uint32_t* maskS = (uint32_t*)(smem + OFF_MS);

    const int tid  = threadIdx.x;
    const int lane = tid & 31;
    const int w    = tid >> 5;     // 0..15
    const int gid  = lane >> 2;    // 0..7
    const int tig  = lane & 3;     // 0..3
    const int wm   = w >> 2;       // row group: rows 32*wm..
    const int wn   = w & 3;        // col slab = head wn
    const int row0 = blockIdx.x * 128;

    // async W copy: pure linear 64KB (already rounded + relayouted)
    auto cpW = [&](const float* __restrict__ WPg, uint32_t* Ws) {
        #pragma unroll
        for (int i = 0; i < 8; i++) {
            int fi = tid + i * 512;          // 0..4095 float4 slots
            uint32_t d = (uint32_t)__cvta_generic_to_shared(Ws + fi * 4);
            asm volatile("cp.async.cg.shared.global [%0], [%1], 16;"
                         :: "r"(d), "l"(WPg + fi * 4) : "memory");
        }
    };

    // ---- issue X LDGs first (longest-latency loads lead the queue) ----
    float4 xv[8];
    #pragma unroll
    for (int i = 0; i < 8; i++) {
        int fi = tid + i * 512;              // 0..4095 float4 slots
        int r = fi >> 5, c4 = fi & 31;
        xv[i] = *(const float4*)(x + (size_t)(row0 + r) * 128 + c4 * 4);
    }

    // ---- Wq (group 0), Wk (group 1) ----
    cpW(WP_rnd[0], Bs0);
    CP_COMMIT();
    cpW(WP_rnd[1], Bs1);
    CP_COMMIT();

    // ---- convert + store X tile (f32 -> tf32, cvt.rna) ----
    #pragma unroll
    for (int i = 0; i < 8; i++) {
        int fi = tid + i * 512;
        int r = fi >> 5, c4 = fi & 31;
        uint4 u;
        u.x = f2tf(xv[i].x); u.y = f2tf(xv[i].y);
        u.z = f2tf(xv[i].z); u.w = f2tf(xv[i].w);
        *(uint4*)(Xs + r * XS_STRIDE + c4 * 4) = u;
    }
    if (tid < 128) maskS[tid] = mask[row0 + tid];
    CP_WAIT(1);                 // Wq arrived (Wk may still be in flight)
    __syncthreads();

    // A ldmatrix bases (two 16-row m-fragments of this warp's 32-row slab)
    const int a_row = wm * 32 + (lane & 15);
    const uint32_t a_base0 =
        (uint32_t)__cvta_generic_to_shared(Xs + a_row * XS_STRIDE + ((lane >> 4) & 1) * 4);
    const uint32_t a_base1 = a_base0 + 16 * XS_STRIDE * 4;

    // B packed-layout per-thread word offset: col = wn*32+gid (+8 per n-frag)
    const uint32_t b_off = (uint32_t)(((wn * 32 + gid) << 3) + 2 * tig);

    const int colb = wn * 32 + 2 * tig;       // acc cols (colb, colb+1) + n*8

    // GEMM: acc = Xs(128x128) @ W; warp tile 32x32; B via LDS.64 pairs
    auto gemm = [&](float acc[2][4][4], const uint32_t* Ws) {
        #pragma unroll
        for (int mf = 0; mf < 2; mf++)
            #pragma unroll
            for (int n = 0; n < 4; n++)
                #pragma unroll
                for (int j = 0; j < 4; j++) acc[mf][n][j] = 0.f;
        const uint32_t* bbase = Ws + b_off;
        #pragma unroll
        for (int kk = 0; kk < 16; kk++) {
            const int k0 = kk * 8;
            uint32_t a0[2], a1[2], a2[2], a3[2];
            ldsm_x4(a0[0], a1[0], a2[0], a3[0], a_base0 + (uint32_t)(k0 * 4));
            ldsm_x4(a0[1], a1[1], a2[1], a3[1], a_base1 + (uint32_t)(k0 * 4));
            const uint32_t* bp = bbase + (kk << 10);
            uint2 b[4];
            #pragma unroll
            for (int n = 0; n < 4; n++)
                b[n] = *(const uint2*)(bp + (n << 6));
            #pragma unroll
            for (int mf = 0; mf < 2; mf++)
                #pragma unroll
                for (int n = 0; n < 4; n++)
                    mma_tf32(acc[mf][n], a0[mf], a1[mf], a2[mf], a3[mf],
                             b[n].x, b[n].y);
        }
    };

    auto bias_add = [&](float acc[2][4][4], const float* __restrict__ bias) {
        #pragma unroll
        for (int n = 0; n < 4; n++) {
            float2 bb = __ldg((const float2*)(bias + colb + n * 8));
            #pragma unroll
            for (int mf = 0; mf < 2; mf++) {
                acc[mf][n][0] += bb.x; acc[mf][n][1] += bb.y;
                acc[mf][n][2] += bb.x; acc[mf][n][3] += bb.y;
            }
        }
    };

    float P[2][2][4];     // attention weights per (mf, half, key atom)
    float rv[2][2];       // residue-valid flag per (mf, half)
    {
        // ---- Q GEMM (only Wq needed; Wk still streaming) ----
        float Qa[2][4][4];
        gemm(Qa, Bs0);
        bias_add(Qa, bq);
        __syncthreads();                 // all warps done reading Bs0

        // Wv -> Bs0 (group 2) flows during K GEMM + softmax
        cpW(WP_rnd[2], Bs0);
        CP_COMMIT();
        CP_WAIT(1);                      // Wk (group 1) arrived; Wv may pend
        __syncthreads();                 // Wk visible to all warps

        // ---- K GEMM ----
        float Ka[2][4][4];
        gemm(Ka, Bs1);
        bias_add(Ka, bk);

        // ---- scores + softmax, registers + shuffles ----
        #pragma unroll
        for (int mf = 0; mf < 2; mf++) {
            #pragma unroll
            for (int half = 0; half < 2; half++) {
                const int rowg = wm * 32 + mf * 16 + half * 8 + gid;
                const int rb   = rowg & ~3;
                float vb[4], sc[4];
                #pragma unroll
                for (int e = 0; e < 4; e++)
                    vb[e] = (maskS[rb | e] != 0u) ? 1.f : 0.f;
                #pragma unroll
                for (int e = 0; e < 4; e++) {
                    const int src = (lane & ~12) | (e << 2);
                    float s = 0.f;
                    #pragma unroll
                    for (int n = 0; n < 4; n++) {
                        #pragma unroll
                        for (int dj = 0; dj < 2; dj++) {
                            int j = half * 2 + dj;
                            s = fmaf(Qa[mf][n][j],
                                     __shfl_sync(0xffffffffu, Ka[mf][n][j], src), s);
                        }
                    }
                    s += __shfl_xor_sync(0xffffffffu, s, 1);
                    s += __shfl_xor_sync(0xffffffffu, s, 2);
                    sc[e] = (vb[e] > 0.f) ? s * 0.17677669529663687f : -1e30f;
                }
                float mx = fmaxf(fmaxf(sc[0], sc[1]), fmaxf(sc[2], sc[3]));
                float ps = 0.f, pe[4];
                #pragma unroll
                for (int e = 0; e < 4; e++) {
                    pe[e] = (vb[e] > 0.f) ? __expf(sc[e] - mx) : 0.f;
                    ps += pe[e];
                }
                float any = vb[0] + vb[1] + vb[2] + vb[3];
                float inv = (any > 0.f) ? (1.f / ps) : 0.f;
                rv[mf][half] = (any > 0.f) ? 1.f : 0.f;
                #pragma unroll
                for (int e = 0; e < 4; e++) P[mf][half][e] = pe[e] * inv;
            }
        }
    }   // Qa, Ka dead

    __syncthreads();                 // all warps done reading Bs1 (K GEMM)

    // Wo -> Bs1 (group 3) flows during V GEMM + P.V + ctx write
    cpW(WP_rnd[3], Bs1);
    CP_COMMIT();
    CP_WAIT(1);                      // Wv (group 2) arrived
    __syncthreads();                 // Wv visible to all warps

    // ---- V GEMM + P·V (registers) ----
    float cx[2][4][4];
    {
        float Va[2][4][4];
        gemm(Va, Bs0);
        bias_add(Va, bv);
        #pragma unroll
        for (int mf = 0; mf < 2; mf++)
            #pragma unroll
            for (int n = 0; n < 4; n++)
                #pragma unroll
                for (int j = 0; j < 4; j++) cx[mf][n][j] = 0.f;
        #pragma unroll
        for (int mf = 0; mf < 2; mf++) {
            #pragma unroll
            for (int half = 0; half < 2; half++) {
                #pragma unroll
                for (int e = 0; e < 4; e++) {
                    const int src = (lane & ~12) | (e << 2);
                    const float pw = P[mf][half][e];
                    #pragma unroll
                    for (int n = 0; n < 4; n++) {
                        #pragma unroll
                        for (int dj = 0; dj < 2; dj++) {
                            int j = half * 2 + dj;
                            cx[mf][n][j] = fmaf(pw,
                                __shfl_sync(0xffffffffu, Va[mf][n][j], src),
                                cx[mf][n][j]);
                        }
                    }
                }
            }
        }
    }   // Va dead

    __syncthreads();            // all warps done reading Xs (V GEMM)

    // ---- ctx -> Xs (tf32, cvt.rna) ----
    #pragma unroll
    for (int mf = 0; mf < 2; mf++) {
        #pragma unroll
        for (int half = 0; half < 2; half++) {
            const int rowg = wm * 32 + mf * 16 + half * 8 + gid;
            #pragma unroll
            for (int n = 0; n < 4; n++) {
                uint2 u;
                u.x = f2tf(cx[mf][n][half * 2 + 0]);
                u.y = f2tf(cx[mf][n][half * 2 + 1]);
                *(uint2*)(Xs + rowg * XS_STRIDE + colb + n * 8) = u;
            }
        }
    }
    CP_WAIT(0);                 // Wo (group 3) arrived
    __syncthreads();            // ctx + Wo visible

    // ---- O GEMM + bias + residue zeroing -> global ----
    {
        float Oa[2][4][4];
        gemm(Oa, Bs1);
        bias_add(Oa, bo);
        #pragma unroll
        for (int mf = 0; mf < 2; mf++) {
            #pragma unroll
            for (int half = 0; half < 2; half++) {
                const int rowg = wm * 32 + mf * 16 + half * 8 + gid;
                const float r = rv[mf][half];
                #pragma unroll
                for (int n = 0; n < 4; n++) {
                    float2 o;
                    o.x = Oa[mf][n][half * 2 + 0] * r;
                    o.y = Oa[mf][n][half * 2 + 1] * r;
                    *(float2*)(out + (size_t)(row0 + rowg) * 128 + colb + n * 8) = o;
                }
            }
        }
    }
}

extern "C" void kernel_launch(void* const* d_in, const int* in_sizes, int n_in,
                              void* d_out, int out_size)
{
    const float*    x    = (const float*)d_in[0];
    const uint32_t* mask = (const uint32_t*)d_in[1];
    const float*    Wq   = (const float*)d_in[2];
    const float*    bq   = (const float*)d_in[3];
    const float*    Wk   = (const float*)d_in[4];
    const float*    bk   = (const float*)d_in[5];
    const float*    Wv   = (const float*)d_in[6];
    const float*    bv   = (const float*)d_in[7];
    const float*    Wo   = (const float*)d_in[8];
    const float*    bo   = (const float*)d_in[9];
    float* out = (float*)d_out;

    const int rows = in_sizes[0] / 128;   // 131072
    const int grid = rows / 128;          // 1024

    prep_kernel<<<64, 128>>>(Wq, Wk, Wv, Wo);

    cudaFuncSetAttribute(laa_kernel, cudaFuncAttributeMaxDynamicSharedMemorySize, SMEM_BYTES);
    laa_kernel<<<grid, 512, SMEM_BYTES>>>(x, mask, bq, bk, bv, bo, out);
}

// round 17
// speedup vs baseline: 1.2228x; 1.0481x over previous
#include <cuda_runtime.h>
#include <cstdint>

#define XS_STRIDE 132   // words: 128 + 4 pad — conflict-free ldmatrix (A)

// smem byte offsets
#define OFF_A   0         // X tile / ctx: 128 x 132 tf32 words (67584 B)
#define OFF_B0  67584     // W packed buffer 0: 16384 words (65536 B)
#define OFF_B1  133120    // W packed buffer 1: 16384 words (65536 B)
#define OFF_MS  198656    // 128 mask words (512 B)
#define SMEM_BYTES 199168

// pre-rounded (tf32, rna) RE-LAYOUTED weights:
// WP[g][(k>>3)*1024 + c*8 + 2*(k&3) + ((k>>2)&1)] = rna(W[g][k][c])
__device__ float WP_rnd[4][16384];

static __device__ __forceinline__ uint32_t f2tf(float f) {
    uint32_t r; asm("cvt.rna.tf32.f32 %0, %1;" : "=r"(r) : "f"(f)); return r;
}

static __device__ __forceinline__ void mma_tf32(float* d,
        uint32_t a0, uint32_t a1, uint32_t a2, uint32_t a3,
        uint32_t b0, uint32_t b1) {
    asm volatile(
        "mma.sync.aligned.m16n8k8.row.col.f32.tf32.tf32.f32 "
        "{%0,%1,%2,%3}, {%4,%5,%6,%7}, {%8,%9}, {%0,%1,%2,%3};\n"
        : "+f"(d[0]), "+f"(d[1]), "+f"(d[2]), "+f"(d[3])
        : "r"(a0), "r"(a1), "r"(a2), "r"(a3), "r"(b0), "r"(b1));
}

static __device__ __forceinline__ void ldsm_x4(uint32_t& r0, uint32_t& r1,
        uint32_t& r2, uint32_t& r3, uint32_t saddr) {
    asm volatile("ldmatrix.sync.aligned.m8n8.x4.shared.b16 {%0,%1,%2,%3}, [%4];"
                 : "=r"(r0), "=r"(r1), "=r"(r2), "=r"(r3) : "r"(saddr));
}

#define CP_COMMIT()  asm volatile("cp.async.commit_group;" ::: "memory")
#define CP_WAIT(n)   asm volatile("cp.async.wait_group %0;" :: "n"(n) : "memory")

// ---- prep: tf32(rna) + relayout, fully coalesced ----
__global__ void prep_kernel(const float* __restrict__ Wq, const float* __restrict__ Wk,
                            const float* __restrict__ Wv, const float* __restrict__ Wo)
{
    const int t  = blockIdx.x * blockDim.x + threadIdx.x;  // 0..8191
    const int c  = t & 127;          // column (contiguous across threads)
    const int kg = (t >> 7) & 15;    // k-group
    const int g  = t >> 11;          // matrix
    const float* src[4] = {Wq, Wk, Wv, Wo};
    const float* W = src[g];

    float v[8];
    #pragma unroll
    for (int j = 0; j < 8; j++)
        v[j] = W[(kg * 8 + j) * 128 + c];

    // perm: word w holds j = (w&1)*4 + (w>>1)
    uint4 u0, u1;
    u0.x = f2tf(v[0]); u0.y = f2tf(v[4]); u0.z = f2tf(v[1]); u0.w = f2tf(v[5]);
    u1.x = f2tf(v[2]); u1.y = f2tf(v[6]); u1.z = f2tf(v[3]); u1.w = f2tf(v[7]);
    uint32_t* dst = (uint32_t*)&WP_rnd[g][kg * 1024 + c * 8];
    *(uint4*)(dst)     = u0;
    *(uint4*)(dst + 4) = u1;
}

__global__ __launch_bounds__(512, 1)
void laa_kernel(const float* __restrict__ x, const uint32_t* __restrict__ mask,
                const float* __restrict__ bq, const float* __restrict__ bk,
                const float* __restrict__ bv, const float* __restrict__ bo,
                float* __restrict__ out)
{
    extern __shared__ char smem[];
    uint32_t* Xs    = (uint32_t*)(smem + OFF_A);
    uint32_t* Bs0   = (uint32_t*)(smem + OFF_B0);
    uint32_t* Bs1   = (uint32_t*)(smem + OFF_B1);
    uint32_t* maskS = (uint32_t*)(smem + OFF_MS);

    const int tid  = threadIdx.x;
    const int lane = tid & 31;
    const int w    = tid >> 5;     // 0..15
    const int gid  = lane >> 2;    // 0..7
    const int tig  = lane & 3;     // 0..3
    const int wm   = w >> 2;       // row group: rows 32*wm..
    const int wn   = w & 3;        // col slab = head wn
    const int row0 = blockIdx.x * 128;

    // async W copy: pure linear 64KB (already rounded + relayouted)
    auto cpW = [&](const float* __restrict__ WPg, uint32_t* Ws) {
        #pragma unroll
        for (int i = 0; i < 8; i++) {
            int fi = tid + i * 512;          // 0..4095 float4 slots
            uint32_t d = (uint32_t)__cvta_generic_to_shared(Ws + fi * 4);
            asm volatile("cp.async.cg.shared.global [%0], [%1], 16;"
                         :: "r"(d), "l"(WPg + fi * 4) : "memory");
        }
    };

    // ---- issue X LDGs first (longest-latency loads lead the queue) ----
    float4 xv[8];
    #pragma unroll
    for (int i = 0; i < 8; i++) {
        int fi = tid + i * 512;              // 0..4095 float4 slots
        int r = fi >> 5, c4 = fi & 31;
        xv[i] = *(const float4*)(x + (size_t)(row0 + r) * 128 + c4 * 4);
    }

    // ---- Wq (group 0), Wk (group 1) ----
    cpW(WP_rnd[0], Bs0);
    CP_COMMIT();
    cpW(WP_rnd[1], Bs1);
    CP_COMMIT();

    // ---- convert + store X tile (f32 -> tf32, cvt.rna) ----
    #pragma unroll
    for (int i = 0; i < 8; i++) {
        int fi = tid + i * 512;
        int r = fi >> 5, c4 = fi & 31;
        uint4 u;
        u.x = f2tf(xv[i].x); u.y = f2tf(xv[i].y);
        u.z = f2tf(xv[i].z); u.w = f2tf(xv[i].w);
        *(uint4*)(Xs + r * XS_STRIDE + c4 * 4) = u;
    }
    if (tid < 128) maskS[tid] = mask[row0 + tid];
    CP_WAIT(1);                 // Wq arrived (Wk may still be in flight)
    __syncthreads();

    // A ldmatrix bases (two 16-row m-fragments of this warp's 32-row slab)
    const int a_row = wm * 32 + (lane & 15);
    const uint32_t a_base0 =
        (uint32_t)__cvta_generic_to_shared(Xs + a_row * XS_STRIDE + ((lane >> 4) & 1) * 4);
    const uint32_t a_base1 = a_base0 + 16 * XS_STRIDE * 4;

    // B packed-layout per-thread word offset: col = wn*32+gid (+8 per n-frag)
    const uint32_t b_off = (uint32_t)(((wn * 32 + gid) << 3) + 2 * tig);

    const int colb = wn * 32 + 2 * tig;       // acc cols (colb, colb+1) + n*8

    // GEMM: acc = Xs(128x128) @ W; warp tile 32x32; B via LDS.64 pairs.
    // Partial unroll (4) keeps code footprint inside the I$ plateau.
    auto gemm = [&](float acc[2][4][4], const uint32_t* Ws) {
        #pragma unroll
        for (int mf = 0; mf < 2; mf++)
            #pragma unroll
            for (int n = 0; n < 4; n++)
                #pragma unroll
                for (int j = 0; j < 4; j++) acc[mf][n][j] = 0.f;
        const uint32_t* bbase = Ws + b_off;
        #pragma unroll 4
        for (int kk = 0; kk < 16; kk++) {
            const int k0 = kk * 8;
            uint32_t a0[2], a1[2], a2[2], a3[2];
            ldsm_x4(a0[0], a1[0], a2[0], a3[0], a_base0 + (uint32_t)(k0 * 4));
            ldsm_x4(a0[1], a1[1], a2[1], a3[1], a_base1 + (uint32_t)(k0 * 4));
            const uint32_t* bp = bbase + (kk << 10);
            uint2 b[4];
            #pragma unroll
            for (int n = 0; n < 4; n++)
                b[n] = *(const uint2*)(bp + (n << 6));
            #pragma unroll
            for (int mf = 0; mf < 2; mf++)
                #pragma unroll
                for (int n = 0; n < 4; n++)
                    mma_tf32(acc[mf][n], a0[mf], a1[mf], a2[mf], a3[mf],
                             b[n].x, b[n].y);
        }
    };

    auto bias_add = [&](float acc[2][4][4], const float* __restrict__ bias) {
        #pragma unroll
        for (int n = 0; n < 4; n++) {
            float2 bb = __ldg((const float2*)(bias + colb + n * 8));
            #pragma unroll
            for (int mf = 0; mf < 2; mf++) {
                acc[mf][n][0] += bb.x; acc[mf][n][1] += bb.y;
                acc[mf][n][2] += bb.x; acc[mf][n][3] += bb.y;
            }
        }
    };

    float P[2][2][4];     // attention weights per (mf, half, key atom)
    float rv[2][2];       // residue-valid flag per (mf, half)
    {
        // ---- Q GEMM (only Wq needed; Wk still streaming) ----
        float Qa[2][4][4];
        gemm(Qa, Bs0);
        bias_add(Qa, bq);
        __syncthreads();                 // all warps done reading Bs0

        // Wv -> Bs0 (group 2) flows during K GEMM + softmax
        cpW(WP_rnd[2], Bs0);
        CP_COMMIT();
        CP_WAIT(1);                      // Wk (group 1) arrived; Wv may pend
        __syncthreads();                 // Wk visible to all warps

        // ---- K GEMM ----
        float Ka[2][4][4];
        gemm(Ka, Bs1);
        bias_add(Ka, bk);

        // ---- scores + softmax, registers + shuffles ----
        #pragma unroll
        for (int mf = 0; mf < 2; mf++) {
            #pragma unroll
            for (int half = 0; half < 2; half++) {
                const int rowg = wm * 32 + mf * 16 + half * 8 + gid;
                const int rb   = rowg & ~3;
                float vb[4], sc[4];
                #pragma unroll
                for (int e = 0; e < 4; e++)
                    vb[e] = (maskS[rb | e] != 0u) ? 1.f : 0.f;
                #pragma unroll
                for (int e = 0; e < 4; e++) {
                    const int src = (lane & ~12) | (e << 2);
                    float s = 0.f;
                    #pragma unroll
                    for (int n = 0; n < 4; n++) {
                        #pragma unroll
                        for (int dj = 0; dj < 2; dj++) {
                            int j = half * 2 + dj;
                            s = fmaf(Qa[mf][n][j],
                                     __shfl_sync(0xffffffffu, Ka[mf][n][j], src), s);
                        }
                    }
                    s += __shfl_xor_sync(0xffffffffu, s, 1);
                    s += __shfl_xor_sync(0xffffffffu, s, 2);
                    sc[e] = (vb[e] > 0.f) ? s * 0.17677669529663687f : -1e30f;
                }
                float mx = fmaxf(fmaxf(sc[0], sc[1]), fmaxf(sc[2], sc[3]));
                float ps = 0.f, pe[4];
                #pragma unroll
                for (int e = 0; e < 4; e++) {
                    pe[e] = (vb[e] > 0.f) ? __expf(sc[e] - mx) : 0.f;
                    ps += pe[e];
                }
                float any = vb[0] + vb[1] + vb[2] + vb[3];
                float inv = (any > 0.f) ? (1.f / ps) : 0.f;
                rv[mf][half] = (any > 0.f) ? 1.f : 0.f;
                #pragma unroll
                for (int e = 0; e < 4; e++) P[mf][half][e] = pe[e] * inv;
            }
        }
    }   // Qa, Ka dead

    __syncthreads();                 // all warps done reading Bs1 (K GEMM)

    // Wo -> Bs1 (group 3) flows during V GEMM + P.V + ctx write
    cpW(WP_rnd[3], Bs1);
    CP_COMMIT();
    CP_WAIT(1);                      // Wv (group 2) arrived
    __syncthreads();                 // Wv visible to all warps

    // ---- V GEMM + P·V (registers) ----
    float cx[2][4][4];
    {
        float Va[2][4][4];
        gemm(Va, Bs0);
        bias_add(Va, bv);
        #pragma unroll
        for (int mf = 0; mf < 2; mf++)
            #pragma unroll
            for (int n = 0; n < 4; n++)
                #pragma unroll
                for (int j = 0; j < 4; j++) cx[mf][n][j] = 0.f;
        #pragma unroll
        for (int mf = 0; mf < 2; mf++) {
            #pragma unroll
            for (int half = 0; half < 2; half++) {
                #pragma unroll
                for (int e = 0; e < 4; e++) {
                    const int src = (lane & ~12) | (e << 2);
                    const float pw = P[mf][half][e];
                    #pragma unroll
                    for (int n = 0; n < 4; n++) {
                        #pragma unroll
                        for (int dj = 0; dj < 2; dj++) {
                            int j = half * 2 + dj;
                            cx[mf][n][j] = fmaf(pw,
                                __shfl_sync(0xffffffffu, Va[mf][n][j], src),
                                cx[mf][n][j]);
                        }
                    }
                }
            }
        }
    }   // Va dead

    __syncthreads();            // all warps done reading Xs (V GEMM)

    // ---- ctx -> Xs (tf32, cvt.rna) ----
    #pragma unroll
    for (int mf = 0; mf < 2; mf++) {
        #pragma unroll
        for (int half = 0; half < 2; half++) {
            const int rowg = wm * 32 + mf * 16 + half * 8 + gid;
            #pragma unroll
            for (int n = 0; n < 4; n++) {
                uint2 u;
                u.x = f2tf(cx[mf][n][half * 2 + 0]);
                u.y = f2tf(cx[mf][n][half * 2 + 1]);
                *(uint2*)(Xs + rowg * XS_STRIDE + colb + n * 8) = u;
            }
        }
    }
    CP_WAIT(0);                 // Wo (group 3) arrived
    __syncthreads();            // ctx + Wo visible

    // ---- O GEMM + bias + residue zeroing -> global ----
    {
        float Oa[2][4][4];
        gemm(Oa, Bs1);
        bias_add(Oa, bo);
        #pragma unroll
        for (int mf = 0; mf < 2; mf++) {
            #pragma unroll
            for (int half = 0; half < 2; half++) {
                const int rowg = wm * 32 + mf * 16 + half * 8 + gid;
                const float r = rv[mf][half];
                #pragma unroll
                for (int n = 0; n < 4; n++) {
                    float2 o;
                    o.x = Oa[mf][n][half * 2 + 0] * r;
                    o.y = Oa[mf][n][half * 2 + 1] * r;
                    *(float2*)(out + (size_t)(row0 + rowg) * 128 + colb + n * 8) = o;
                }
            }
        }
    }
}

extern "C" void kernel_launch(void* const* d_in, const int* in_sizes, int n_in,
                              void* d_out, int out_size)
{
    const float*    x    = (const float*)d_in[0];
    const uint32_t* mask = (const uint32_t*)d_in[1];
    const float*    Wq   = (const float*)d_in[2];
    const float*    bq   = (const float*)d_in[3];
    const float*    Wk   = (const float*)d_in[4];
    const float*    bk   = (const float*)d_in[5];
    const float*    Wv   = (const float*)d_in[6];
    const float*    bv   = (const float*)d_in[7];
    const float*    Wo   = (const float*)d_in[8];
    const float*    bo   = (const float*)d_in[9];
    float* out = (float*)d_out;

    const int rows = in_sizes[0] / 128;   // 131072
    const int grid = rows / 128;          // 1024

    prep_kernel<<<64, 128>>>(Wq, Wk, Wv, Wo);

    cudaFuncSetAttribute(laa_kernel, cudaFuncAttributeMaxDynamicSharedMemorySize, SMEM_BYTES);
    laa_kernel<<<grid, 512, SMEM_BYTES>>>(x, mask, bq, bk, bv, bo, out);
}